// round 12
// baseline (speedup 1.0000x reference)
#include <cuda_runtime.h>
#include <cuda_fp16.h>
#include <cstdint>

// Problem constants
#define T_TOK   4096
#define DM      1024
#define HID     2048
#define NEXP    8
#define PADMAX  9216
#define MAXROWS (PADMAX + T_TOK)     // 13312

// GEMM tiling (half-precision element counts)
#define BM 128
#define BN 128
#define KC 64               // halves per k-slice
#define ASTR 72             // row stride in halves (64 + 8 pad; 144B rows, conflict-free)
#define ROWB (ASTR * 2)     // 144 bytes
#define STAGES 3
#define SA (BM * ASTR)      // halves per tile (9216)
#define NTHREADS 512        // 16 warps: 4(m) x 4(n), warp tile 32x32

// ---------------- scratch (device globals: allocation-free) ----------------
__device__ int    g_counts[NEXP];
__device__ int    g_seg[NEXP + 2];
__device__ int    g_cursor[NEXP];
__device__ int    g_topk_idx[T_TOK * 2];
__device__ float  g_topk_gate[T_TOK * 2];
__device__ int    g_perm_token[MAXROWS];
__device__ int    g_inv[T_TOK * 2];
__device__ __half g_xh[(size_t)T_TOK * DM];           // fp16 X
__device__ __half g_w1t[(size_t)NEXP * HID * DM];     // [e][h][d]
__device__ __half g_w3t[(size_t)NEXP * HID * DM];
__device__ __half g_w2t[(size_t)NEXP * DM * HID];     // [e][d][h]
__device__ __half g_sw1t[(size_t)HID * DM];
__device__ __half g_sw3t[(size_t)HID * DM];
__device__ __half g_sw2t[(size_t)DM * HID];
__device__ __half g_acth[(size_t)MAXROWS * HID];      // fp16 SwiGLU activations
__device__ float  g_y[(size_t)MAXROWS * DM];          // fp32 expert outputs

// ---------------- helpers ----------------
__device__ __forceinline__ uint32_t smem_u32(const void* p) {
    return (uint32_t)__cvta_generic_to_shared(p);
}
__device__ __forceinline__ void mma_f16(float* d, const unsigned* a, const unsigned* b) {
    asm volatile(
        "mma.sync.aligned.m16n8k16.row.col.f32.f16.f16.f32 "
        "{%0,%1,%2,%3}, {%4,%5,%6,%7}, {%8,%9}, {%0,%1,%2,%3};\n"
        : "+f"(d[0]), "+f"(d[1]), "+f"(d[2]), "+f"(d[3])
        : "r"(a[0]), "r"(a[1]), "r"(a[2]), "r"(a[3]), "r"(b[0]), "r"(b[1]));
}
__device__ __forceinline__ void ldsm_x4(unsigned* r, uint32_t addr) {
    asm volatile("ldmatrix.sync.aligned.m8n8.x4.shared.b16 {%0,%1,%2,%3}, [%4];"
                 : "=r"(r[0]), "=r"(r[1]), "=r"(r[2]), "=r"(r[3]) : "r"(addr));
}
__device__ __forceinline__ void cp16(uint32_t dst, const __half* src) {
    asm volatile("cp.async.cg.shared.global [%0], [%1], 16;\n" :: "r"(dst), "l"(src));
}
__device__ __forceinline__ void cp_commit() { asm volatile("cp.async.commit_group;\n"); }
template <int N> __device__ __forceinline__ void cp_wait() {
    asm volatile("cp.async.wait_group %0;\n" :: "n"(N));
}
__device__ __forceinline__ float silu_f(float h) {
    return __fdividef(h, 1.0f + __expf(-h));
}

// ---------------- stage 0: reset ----------------
__global__ void reset_kernel() {
    int i = blockIdx.x * blockDim.x + threadIdx.x;
    if (i < NEXP) g_counts[i] = 0;
    for (int p = i; p < MAXROWS; p += gridDim.x * blockDim.x) g_perm_token[p] = 0;
}

// ---------------- convert X -> fp16 ----------------
__global__ void cvt_x_kernel(const float* __restrict__ X) {
    int i = blockIdx.x * blockDim.x + threadIdx.x;
    float4 v = reinterpret_cast<const float4*>(X)[i];
    __half2* dst = reinterpret_cast<__half2*>(g_xh);
    dst[2 * i]     = __floats2half2_rn(v.x, v.y);
    dst[2 * i + 1] = __floats2half2_rn(v.z, v.w);
}

// ---------------- convert + transpose weights: in[R][C] fp32 -> out[C][R] fp16 ----------------
__global__ __launch_bounds__(256) void transpose_cvt_kernel(
    const float* __restrict__ in, __half* __restrict__ out, int R, int C) {
    __shared__ __half tile[64][66];
    size_t moff = (size_t)blockIdx.z * R * C;
    in += moff; out += moff;
    int c0 = blockIdx.x * 64, r0 = blockIdx.y * 64;

    int fc = threadIdx.x & 15, row4 = threadIdx.x >> 4;
#pragma unroll
    for (int p = 0; p < 4; p++) {
        int r = row4 + p * 16;
        float4 v = *reinterpret_cast<const float4*>(in + (size_t)(r0 + r) * C + c0 + fc * 4);
        tile[fc * 4 + 0][r] = __float2half_rn(v.x);
        tile[fc * 4 + 1][r] = __float2half_rn(v.y);
        tile[fc * 4 + 2][r] = __float2half_rn(v.z);
        tile[fc * 4 + 3][r] = __float2half_rn(v.w);
    }
    __syncthreads();

    int oc = threadIdx.x >> 2, seg = threadIdx.x & 3;
    unsigned u[8];
#pragma unroll
    for (int j = 0; j < 8; j++) {
        __half2 hh = __halves2half2(tile[oc][seg * 16 + 2 * j], tile[oc][seg * 16 + 2 * j + 1]);
        u[j] = *reinterpret_cast<unsigned*>(&hh);
    }
    uint4* dst = reinterpret_cast<uint4*>(out + (size_t)(c0 + oc) * R + r0 + seg * 16);
    dst[0] = make_uint4(u[0], u[1], u[2], u[3]);
    dst[1] = make_uint4(u[4], u[5], u[6], u[7]);
}

// ---------------- stage 1: router ----------------
__global__ __launch_bounds__(256) void router_kernel(const float* __restrict__ X,
                                                     const float* __restrict__ WR) {
    int warp = threadIdx.x >> 5, lane = threadIdx.x & 31;
    int t = blockIdx.x * 8 + warp;
    if (t >= T_TOK) return;

    float acc[8];
#pragma unroll
    for (int e = 0; e < 8; e++) acc[e] = 0.0f;

    const float* xr = X + (size_t)t * DM;
    for (int i = lane; i < DM; i += 32) {
        float xv = xr[i];
        const float4* w = reinterpret_cast<const float4*>(WR + (size_t)i * NEXP);
        float4 w0 = w[0], w1 = w[1];
        acc[0] += xv * w0.x; acc[1] += xv * w0.y; acc[2] += xv * w0.z; acc[3] += xv * w0.w;
        acc[4] += xv * w1.x; acc[5] += xv * w1.y; acc[6] += xv * w1.z; acc[7] += xv * w1.w;
    }
#pragma unroll
    for (int e = 0; e < 8; e++)
#pragma unroll
        for (int off = 16; off > 0; off >>= 1)
            acc[e] += __shfl_xor_sync(0xffffffffu, acc[e], off);

    if (lane == 0) {
        int i0 = 0; float v0 = acc[0];
#pragma unroll
        for (int e = 1; e < 8; e++) if (acc[e] > v0) { v0 = acc[e]; i0 = e; }
        int i1 = -1; float v1 = -3.4e38f;
#pragma unroll
        for (int e = 0; e < 8; e++) if (e != i0 && acc[e] > v1) { v1 = acc[e]; i1 = e; }
        float r  = expf(v1 - v0);
        float g0 = 1.0f / (1.0f + r);
        float g1 = r / (1.0f + r);
        g_topk_idx[t * 2]      = i0;
        g_topk_idx[t * 2 + 1]  = i1;
        g_topk_gate[t * 2]     = g0;
        g_topk_gate[t * 2 + 1] = g1;
        atomicAdd(&g_counts[i0], 1);
        atomicAdd(&g_counts[i1], 1);
    }
}

// ---------------- stage 2: segment scan ----------------
__global__ void scan_kernel() {
    if (threadIdx.x == 0 && blockIdx.x == 0) {
        int s = 0;
        for (int e = 0; e < NEXP; e++) {
            g_seg[e] = s;
            g_cursor[e] = s;
            s += (g_counts[e] + BM - 1) & ~(BM - 1);
        }
        g_seg[NEXP] = s;
        g_seg[NEXP + 1] = s + T_TOK;
    }
}

// ---------------- stage 3: build permutation ----------------
__global__ void fill_kernel() {
    int i = blockIdx.x * blockDim.x + threadIdx.x;
    if (i < T_TOK * 2) {
        int e = g_topk_idx[i];
        int p = atomicAdd(&g_cursor[e], 1);
        g_perm_token[p] = i >> 1;
        g_inv[i] = p;
    } else if (i < T_TOK * 3) {
        int t = i - T_TOK * 2;
        g_perm_token[g_seg[NEXP] + t] = t;
    }
}

// ======================================================================
// fp16 mma.sync grouped GEMMs
// 512 threads, 4x4 warp grid (32x32 warp tiles), KC=64, ldmatrix.x4,
// 3-stage cp.async. 4 warps/SMSP to fill ldsm->mma and barrier bubbles.
// ======================================================================

extern __shared__ __align__(16) __half smh[];

// stage 4: SwiGLU up-projection: ACT = silu(X W1) * (X W3), fp16 out
__global__ __launch_bounds__(NTHREADS, 1) void gemm1_kernel(
    const __half* __restrict__ W1T, const __half* __restrict__ W3T,
    const __half* __restrict__ SW1T, const __half* __restrict__ SW3T) {
    int base = blockIdx.y * BM;
    if (base >= g_seg[NEXP + 1]) return;
    int e = 0;
    while (g_seg[e + 1] <= base) e++;
    const __half* W1e = (e < NEXP) ? W1T + (size_t)e * HID * DM : SW1T;
    const __half* W3e = (e < NEXP) ? W3T + (size_t)e * HID * DM : SW3T;
    int nb = blockIdx.x * BN;

    int tid = threadIdx.x, lane = tid & 31, warp = tid >> 5;
    int wm = warp & 3, wn = warp >> 2;     // 4x4 warps, warp tile 32(m)x32(n)

    uint32_t sbase = smem_u32(smh);

    // producer mapping: per tile 128 rows x 8 chunks(16B); 2 rows per thread
    int ch = tid & 7;
    int rows[2];
    const __half* asrc[2];
    uint32_t dstoff[2];
#pragma unroll
    for (int i = 0; i < 2; i++) {
        int r = (tid >> 3) + 64 * i;
        rows[i] = r;
        asrc[i] = g_xh + (size_t)g_perm_token[base + r] * DM + ch * 8;
        dstoff[i] = (uint32_t)(r * ROWB + ch * 16);
    }

    // A ldmatrix offsets (x4: 16 rows x 2 k-chunks)
    uint32_t aoff[2];
#pragma unroll
    for (int mt = 0; mt < 2; mt++)
        aoff[mt] = (uint32_t)((wm * 32 + mt * 16 + (lane & 15)) * ROWB + (lane >> 4) * 16);
    // B ldmatrix.x4 offsets: pair p covers n-rows [wn*32 + p*16, +16)
    uint32_t boff4[2];
#pragma unroll
    for (int p = 0; p < 2; p++)
        boff4[p] = (uint32_t)((wn * 32 + p * 16 + ((lane >> 4) & 1) * 8 + (lane & 7)) * ROWB
                              + ((lane >> 3) & 1) * 16);

    float acc1[2][4][4], acc3[2][4][4];
#pragma unroll
    for (int mt = 0; mt < 2; mt++)
#pragma unroll
        for (int nt = 0; nt < 4; nt++)
#pragma unroll
            for (int q = 0; q < 4; q++) { acc1[mt][nt][q] = 0.0f; acc3[mt][nt][q] = 0.0f; }

    const int nsl = DM / KC;   // 16

    auto issue = [&](int s) {
        uint32_t tb = sbase + (uint32_t)((s % STAGES) * 3 * SA * 2);
        int kb = s * KC;
#pragma unroll
        for (int i = 0; i < 2; i++) {
            cp16(tb + dstoff[i], asrc[i] + kb);
            cp16(tb + SA * 2 + dstoff[i], W1e + (size_t)(nb + rows[i]) * DM + kb + ch * 8);
            cp16(tb + 2 * SA * 2 + dstoff[i], W3e + (size_t)(nb + rows[i]) * DM + kb + ch * 8);
        }
        cp_commit();
    };

    issue(0);
    issue(1);

    for (int s = 0; s < nsl; s++) {
        if (s + 1 < nsl) cp_wait<1>(); else cp_wait<0>();
        __syncthreads();
        if (s + 2 < nsl) issue(s + 2);

        uint32_t tb = sbase + (uint32_t)((s % STAGES) * 3 * SA * 2);
        uint32_t aT = tb, b1T = tb + SA * 2, b3T = tb + 2 * SA * 2;
#pragma unroll
        for (int ks = 0; ks < 4; ks++) {
            uint32_t ko = ks * 32;   // 16 halves = 32 bytes
            unsigned a[2][4];
#pragma unroll
            for (int mt = 0; mt < 2; mt++) ldsm_x4(a[mt], aT + aoff[mt] + ko);
            unsigned b1[2][4], b3[2][4];
#pragma unroll
            for (int p = 0; p < 2; p++) {
                ldsm_x4(b1[p], b1T + boff4[p] + ko);
                ldsm_x4(b3[p], b3T + boff4[p] + ko);
            }
#pragma unroll
            for (int mt = 0; mt < 2; mt++)
#pragma unroll
                for (int p = 0; p < 2; p++) {
                    mma_f16(acc1[mt][2 * p],     a[mt], &b1[p][0]);
                    mma_f16(acc1[mt][2 * p + 1], a[mt], &b1[p][2]);
                    mma_f16(acc3[mt][2 * p],     a[mt], &b3[p][0]);
                    mma_f16(acc3[mt][2 * p + 1], a[mt], &b3[p][2]);
                }
        }
    }

    // epilogue: act = silu(h1) * h3, fp16
    int g = lane >> 2, tig = lane & 3;
#pragma unroll
    for (int mt = 0; mt < 2; mt++) {
#pragma unroll
        for (int nt = 0; nt < 4; nt++) {
            int r0 = base + wm * 32 + mt * 16 + g;
            int c  = nb + wn * 32 + nt * 8 + tig * 2;
            __half2 h0 = __floats2half2_rn(silu_f(acc1[mt][nt][0]) * acc3[mt][nt][0],
                                           silu_f(acc1[mt][nt][1]) * acc3[mt][nt][1]);
            __half2 h1 = __floats2half2_rn(silu_f(acc1[mt][nt][2]) * acc3[mt][nt][2],
                                           silu_f(acc1[mt][nt][3]) * acc3[mt][nt][3]);
            *reinterpret_cast<__half2*>(g_acth + (size_t)r0 * HID + c)       = h0;
            *reinterpret_cast<__half2*>(g_acth + (size_t)(r0 + 8) * HID + c) = h1;
        }
    }
}

// stage 5: down-projection: Y = ACT @ W2, fp32 out
__global__ __launch_bounds__(NTHREADS, 1) void gemm2_kernel(
    const __half* __restrict__ W2T, const __half* __restrict__ SW2T) {
    int base = blockIdx.y * BM;
    if (base >= g_seg[NEXP + 1]) return;
    int e = 0;
    while (g_seg[e + 1] <= base) e++;
    const __half* W2e = (e < NEXP) ? W2T + (size_t)e * DM * HID : SW2T;
    int nb = blockIdx.x * BN;

    int tid = threadIdx.x, lane = tid & 31, warp = tid >> 5;
    int wm = warp & 3, wn = warp >> 2;

    uint32_t sbase = smem_u32(smh);

    int ch = tid & 7;
    int rows[2];
    uint32_t dstoff[2];
#pragma unroll
    for (int i = 0; i < 2; i++) {
        int r = (tid >> 3) + 64 * i;
        rows[i] = r;
        dstoff[i] = (uint32_t)(r * ROWB + ch * 16);
    }

    uint32_t aoff[2];
#pragma unroll
    for (int mt = 0; mt < 2; mt++)
        aoff[mt] = (uint32_t)((wm * 32 + mt * 16 + (lane & 15)) * ROWB + (lane >> 4) * 16);
    uint32_t boff4[2];
#pragma unroll
    for (int p = 0; p < 2; p++)
        boff4[p] = (uint32_t)((wn * 32 + p * 16 + ((lane >> 4) & 1) * 8 + (lane & 7)) * ROWB
                              + ((lane >> 3) & 1) * 16);

    float acc[2][4][4];
#pragma unroll
    for (int mt = 0; mt < 2; mt++)
#pragma unroll
        for (int nt = 0; nt < 4; nt++)
#pragma unroll
            for (int q = 0; q < 4; q++) acc[mt][nt][q] = 0.0f;

    const int nsl = HID / KC;   // 32

    auto issue = [&](int s) {
        uint32_t tb = sbase + (uint32_t)((s % STAGES) * 2 * SA * 2);
        int kb = s * KC;
#pragma unroll
        for (int i = 0; i < 2; i++) {
            cp16(tb + dstoff[i], g_acth + (size_t)(base + rows[i]) * HID + kb + ch * 8);
            cp16(tb + SA * 2 + dstoff[i], W2e + (size_t)(nb + rows[i]) * HID + kb + ch * 8);
        }
        cp_commit();
    };

    issue(0);
    issue(1);

    for (int s = 0; s < nsl; s++) {
        if (s + 1 < nsl) cp_wait<1>(); else cp_wait<0>();
        __syncthreads();
        if (s + 2 < nsl) issue(s + 2);

        uint32_t tb = sbase + (uint32_t)((s % STAGES) * 2 * SA * 2);
        uint32_t aT = tb, bT = tb + SA * 2;
#pragma unroll
        for (int ks = 0; ks < 4; ks++) {
            uint32_t ko = ks * 32;
            unsigned a[2][4];
#pragma unroll
            for (int mt = 0; mt < 2; mt++) ldsm_x4(a[mt], aT + aoff[mt] + ko);
            unsigned b[2][4];
#pragma unroll
            for (int p = 0; p < 2; p++) ldsm_x4(b[p], bT + boff4[p] + ko);
#pragma unroll
            for (int mt = 0; mt < 2; mt++)
#pragma unroll
                for (int p = 0; p < 2; p++) {
                    mma_f16(acc[mt][2 * p],     a[mt], &b[p][0]);
                    mma_f16(acc[mt][2 * p + 1], a[mt], &b[p][2]);
                }
        }
    }

    int g = lane >> 2, tig = lane & 3;
#pragma unroll
    for (int mt = 0; mt < 2; mt++) {
#pragma unroll
        for (int nt = 0; nt < 4; nt++) {
            int r0 = base + wm * 32 + mt * 16 + g;
            int c  = nb + wn * 32 + nt * 8 + tig * 2;
            float2 o0, o1;
            o0.x = acc[mt][nt][0]; o0.y = acc[mt][nt][1];
            o1.x = acc[mt][nt][2]; o1.y = acc[mt][nt][3];
            *reinterpret_cast<float2*>(g_y + (size_t)r0 * DM + c)       = o0;
            *reinterpret_cast<float2*>(g_y + (size_t)(r0 + 8) * DM + c) = o1;
        }
    }
}

// ---------------- stage 6: combine shared + gated routed (float4) ----------------
__global__ void combine_kernel(float* __restrict__ OUT) {
    int i = blockIdx.x * blockDim.x + threadIdx.x;   // over float4s
    if (i >= T_TOK * DM / 4) return;
    int t  = i >> 8;            // DM/4 = 256 float4 per token
    int d4 = i & 255;
    int s8 = g_seg[NEXP];
    int p0 = g_inv[t * 2];
    int p1 = g_inv[t * 2 + 1];
    float g0 = g_topk_gate[t * 2];
    float g1 = g_topk_gate[t * 2 + 1];
    float4 vs = *reinterpret_cast<const float4*>(g_y + (size_t)(s8 + t) * DM + d4 * 4);
    float4 v0 = *reinterpret_cast<const float4*>(g_y + (size_t)p0 * DM + d4 * 4);
    float4 v1 = *reinterpret_cast<const float4*>(g_y + (size_t)p1 * DM + d4 * 4);
    float4 o;
    o.x = vs.x + g0 * v0.x + g1 * v1.x;
    o.y = vs.y + g0 * v0.y + g1 * v1.y;
    o.z = vs.z + g0 * v0.z + g1 * v1.z;
    o.w = vs.w + g0 * v0.w + g1 * v1.w;
    reinterpret_cast<float4*>(OUT)[i] = o;
}

// ---------------- launch ----------------
#define G1_SMEM (STAGES * 3 * SA * 2)   // 165888 bytes
#define G2_SMEM (STAGES * 2 * SA * 2)   // 110592 bytes

extern "C" void kernel_launch(void* const* d_in, const int* in_sizes, int n_in,
                              void* d_out, int out_size) {
    (void)in_sizes; (void)n_in; (void)out_size;
    const float* x   = (const float*)d_in[0];
    const float* wr  = (const float*)d_in[1];
    const float* w1  = (const float*)d_in[2];
    const float* w3  = (const float*)d_in[3];
    const float* w2  = (const float*)d_in[4];
    const float* sw1 = (const float*)d_in[5];
    const float* sw3 = (const float*)d_in[6];
    const float* sw2 = (const float*)d_in[7];
    float* out = (float*)d_out;

    __half *w1t, *w3t, *w2t, *sw1t, *sw3t, *sw2t;
    cudaGetSymbolAddress((void**)&w1t,  g_w1t);
    cudaGetSymbolAddress((void**)&w3t,  g_w3t);
    cudaGetSymbolAddress((void**)&w2t,  g_w2t);
    cudaGetSymbolAddress((void**)&sw1t, g_sw1t);
    cudaGetSymbolAddress((void**)&sw3t, g_sw3t);
    cudaGetSymbolAddress((void**)&sw2t, g_sw2t);

    cudaFuncSetAttribute(gemm1_kernel, cudaFuncAttributeMaxDynamicSharedMemorySize, G1_SMEM);
    cudaFuncSetAttribute(gemm2_kernel, cudaFuncAttributeMaxDynamicSharedMemorySize, G2_SMEM);

    reset_kernel<<<52, 256>>>();
    router_kernel<<<512, 256>>>(x, wr);
    scan_kernel<<<1, 32>>>();
    fill_kernel<<<48, 256>>>();

    cvt_x_kernel<<<(T_TOK * DM / 4) / 256, 256>>>(x);
    transpose_cvt_kernel<<<dim3(HID / 64, DM / 64, NEXP), 256>>>(w1, w1t, DM, HID);
    transpose_cvt_kernel<<<dim3(HID / 64, DM / 64, NEXP), 256>>>(w3, w3t, DM, HID);
    transpose_cvt_kernel<<<dim3(DM / 64, HID / 64, NEXP), 256>>>(w2, w2t, HID, DM);
    transpose_cvt_kernel<<<dim3(HID / 64, DM / 64, 1), 256>>>(sw1, sw1t, DM, HID);
    transpose_cvt_kernel<<<dim3(HID / 64, DM / 64, 1), 256>>>(sw3, sw3t, DM, HID);
    transpose_cvt_kernel<<<dim3(DM / 64, HID / 64, 1), 256>>>(sw2, sw2t, HID, DM);

    gemm1_kernel<<<dim3(HID / BN, MAXROWS / BM), NTHREADS, G1_SMEM>>>(w1t, w3t, sw1t, sw3t);
    gemm2_kernel<<<dim3(DM / BN, MAXROWS / BM), NTHREADS, G2_SMEM>>>(w2t, sw2t);

    combine_kernel<<<(T_TOK * DM / 4 + 255) / 256, 256>>>(out);
}

// round 13
// speedup vs baseline: 1.0240x; 1.0240x over previous
#include <cuda_runtime.h>
#include <cuda_fp16.h>
#include <cstdint>

// Problem constants
#define T_TOK   4096
#define DM      1024
#define HID     2048
#define NEXP    8
#define PADMAX  9216
#define MAXROWS (PADMAX + T_TOK)     // 13312

// GEMM tiling (half-precision element counts)
#define BM 128
#define BN 128
#define KC 64               // halves per k-slice
#define ASTR 72             // row stride in halves (64 + 8 pad; 144B rows, conflict-free)
#define ROWB (ASTR * 2)     // 144 bytes
#define STAGES 3
#define SA (BM * ASTR)      // halves per tile (9216)

// ---------------- scratch (device globals: allocation-free) ----------------
__device__ int    g_counts[NEXP];
__device__ int    g_seg[NEXP + 2];
__device__ int    g_cursor[NEXP];
__device__ int    g_topk_idx[T_TOK * 2];
__device__ float  g_topk_gate[T_TOK * 2];
__device__ int    g_perm_token[MAXROWS];
__device__ int    g_inv[T_TOK * 2];
__device__ __half g_xh[(size_t)T_TOK * DM];           // fp16 X
__device__ __half g_w1t[(size_t)NEXP * HID * DM];     // [e][h][d]
__device__ __half g_w3t[(size_t)NEXP * HID * DM];
__device__ __half g_w2t[(size_t)NEXP * DM * HID];     // [e][d][h]
__device__ __half g_sw1t[(size_t)HID * DM];
__device__ __half g_sw3t[(size_t)HID * DM];
__device__ __half g_sw2t[(size_t)DM * HID];
__device__ __half g_acth[(size_t)MAXROWS * HID];      // fp16 SwiGLU activations
__device__ float  g_y[(size_t)MAXROWS * DM];          // fp32 expert outputs

// ---------------- helpers ----------------
__device__ __forceinline__ uint32_t smem_u32(const void* p) {
    return (uint32_t)__cvta_generic_to_shared(p);
}
__device__ __forceinline__ void mma_f16(float* d, const unsigned* a, const unsigned* b) {
    asm volatile(
        "mma.sync.aligned.m16n8k16.row.col.f32.f16.f16.f32 "
        "{%0,%1,%2,%3}, {%4,%5,%6,%7}, {%8,%9}, {%0,%1,%2,%3};\n"
        : "+f"(d[0]), "+f"(d[1]), "+f"(d[2]), "+f"(d[3])
        : "r"(a[0]), "r"(a[1]), "r"(a[2]), "r"(a[3]), "r"(b[0]), "r"(b[1]));
}
__device__ __forceinline__ void ldsm_x4(unsigned* r, uint32_t addr) {
    asm volatile("ldmatrix.sync.aligned.m8n8.x4.shared.b16 {%0,%1,%2,%3}, [%4];"
                 : "=r"(r[0]), "=r"(r[1]), "=r"(r[2]), "=r"(r[3]) : "r"(addr));
}
__device__ __forceinline__ void cp16(uint32_t dst, const __half* src) {
    asm volatile("cp.async.cg.shared.global [%0], [%1], 16;\n" :: "r"(dst), "l"(src));
}
__device__ __forceinline__ void cp_commit() { asm volatile("cp.async.commit_group;\n"); }
template <int N> __device__ __forceinline__ void cp_wait() {
    asm volatile("cp.async.wait_group %0;\n" :: "n"(N));
}
__device__ __forceinline__ float silu_f(float h) {
    return __fdividef(h, 1.0f + __expf(-h));
}

// ---------------- stage 0: reset ----------------
__global__ void reset_kernel() {
    int i = blockIdx.x * blockDim.x + threadIdx.x;
    if (i < NEXP) g_counts[i] = 0;
    for (int p = i; p < MAXROWS; p += gridDim.x * blockDim.x) g_perm_token[p] = 0;
}

// ---------------- convert X -> fp16 ----------------
__global__ void cvt_x_kernel(const float* __restrict__ X) {
    int i = blockIdx.x * blockDim.x + threadIdx.x;
    float4 v = reinterpret_cast<const float4*>(X)[i];
    __half2* dst = reinterpret_cast<__half2*>(g_xh);
    dst[2 * i]     = __floats2half2_rn(v.x, v.y);
    dst[2 * i + 1] = __floats2half2_rn(v.z, v.w);
}

// ---------------- convert + transpose: in[R][C] fp32 -> out[C][R] fp16 ----------------
__device__ __forceinline__ void transpose_cvt_body(
    const float* __restrict__ in, __half* __restrict__ out, int R, int C) {
    __shared__ __half tile[64][66];
    int c0 = blockIdx.x * 64, r0 = blockIdx.y * 64;

    int fc = threadIdx.x & 15, row4 = threadIdx.x >> 4;
#pragma unroll
    for (int p = 0; p < 4; p++) {
        int r = row4 + p * 16;
        float4 v = *reinterpret_cast<const float4*>(in + (size_t)(r0 + r) * C + c0 + fc * 4);
        tile[fc * 4 + 0][r] = __float2half_rn(v.x);
        tile[fc * 4 + 1][r] = __float2half_rn(v.y);
        tile[fc * 4 + 2][r] = __float2half_rn(v.z);
        tile[fc * 4 + 3][r] = __float2half_rn(v.w);
    }
    __syncthreads();

    int oc = threadIdx.x >> 2, seg = threadIdx.x & 3;
    unsigned u[8];
#pragma unroll
    for (int j = 0; j < 8; j++) {
        __half2 hh = __halves2half2(tile[oc][seg * 16 + 2 * j], tile[oc][seg * 16 + 2 * j + 1]);
        u[j] = *reinterpret_cast<unsigned*>(&hh);
    }
    uint4* dst = reinterpret_cast<uint4*>(out + (size_t)(c0 + oc) * R + r0 + seg * 16);
    dst[0] = make_uint4(u[0], u[1], u[2], u[3]);
    dst[1] = make_uint4(u[4], u[5], u[6], u[7]);
}

// merged: all up-projection weights (w1 x8, w3 x8, sw1, sw3); R=DM, C=HID
__global__ __launch_bounds__(256) void transpose_up_kernel(
    const float* __restrict__ w1, const float* __restrict__ w3,
    const float* __restrict__ sw1, const float* __restrict__ sw3) {
    int z = blockIdx.z;
    const float* in;
    __half* out;
    if (z < 8)       { in = w1 + (size_t)z * DM * HID;        out = g_w1t + (size_t)z * HID * DM; }
    else if (z < 16) { in = w3 + (size_t)(z - 8) * DM * HID;  out = g_w3t + (size_t)(z - 8) * HID * DM; }
    else if (z == 16){ in = sw1;                              out = g_sw1t; }
    else             { in = sw3;                              out = g_sw3t; }
    transpose_cvt_body(in, out, DM, HID);
}

// merged: all down-projection weights (w2 x8, sw2); R=HID, C=DM
__global__ __launch_bounds__(256) void transpose_down_kernel(
    const float* __restrict__ w2, const float* __restrict__ sw2) {
    int z = blockIdx.z;
    const float* in;
    __half* out;
    if (z < 8) { in = w2 + (size_t)z * HID * DM; out = g_w2t + (size_t)z * DM * HID; }
    else       { in = sw2;                       out = g_sw2t; }
    transpose_cvt_body(in, out, HID, DM);
}

// ---------------- stage 1: router ----------------
__global__ __launch_bounds__(256) void router_kernel(const float* __restrict__ X,
                                                     const float* __restrict__ WR) {
    int warp = threadIdx.x >> 5, lane = threadIdx.x & 31;
    int t = blockIdx.x * 8 + warp;
    if (t >= T_TOK) return;

    float acc[8];
#pragma unroll
    for (int e = 0; e < 8; e++) acc[e] = 0.0f;

    const float* xr = X + (size_t)t * DM;
    for (int i = lane; i < DM; i += 32) {
        float xv = xr[i];
        const float4* w = reinterpret_cast<const float4*>(WR + (size_t)i * NEXP);
        float4 w0 = w[0], w1 = w[1];
        acc[0] += xv * w0.x; acc[1] += xv * w0.y; acc[2] += xv * w0.z; acc[3] += xv * w0.w;
        acc[4] += xv * w1.x; acc[5] += xv * w1.y; acc[6] += xv * w1.z; acc[7] += xv * w1.w;
    }
#pragma unroll
    for (int e = 0; e < 8; e++)
#pragma unroll
        for (int off = 16; off > 0; off >>= 1)
            acc[e] += __shfl_xor_sync(0xffffffffu, acc[e], off);

    if (lane == 0) {
        int i0 = 0; float v0 = acc[0];
#pragma unroll
        for (int e = 1; e < 8; e++) if (acc[e] > v0) { v0 = acc[e]; i0 = e; }
        int i1 = -1; float v1 = -3.4e38f;
#pragma unroll
        for (int e = 0; e < 8; e++) if (e != i0 && acc[e] > v1) { v1 = acc[e]; i1 = e; }
        float r  = expf(v1 - v0);
        float g0 = 1.0f / (1.0f + r);
        float g1 = r / (1.0f + r);
        g_topk_idx[t * 2]      = i0;
        g_topk_idx[t * 2 + 1]  = i1;
        g_topk_gate[t * 2]     = g0;
        g_topk_gate[t * 2 + 1] = g1;
        atomicAdd(&g_counts[i0], 1);
        atomicAdd(&g_counts[i1], 1);
    }
}

// ---------------- stage 2: segment scan ----------------
__global__ void scan_kernel() {
    if (threadIdx.x == 0 && blockIdx.x == 0) {
        int s = 0;
        for (int e = 0; e < NEXP; e++) {
            g_seg[e] = s;
            g_cursor[e] = s;
            s += (g_counts[e] + BM - 1) & ~(BM - 1);
        }
        g_seg[NEXP] = s;
        g_seg[NEXP + 1] = s + T_TOK;
    }
}

// ---------------- stage 3: build permutation ----------------
__global__ void fill_kernel() {
    int i = blockIdx.x * blockDim.x + threadIdx.x;
    if (i < T_TOK * 2) {
        int e = g_topk_idx[i];
        int p = atomicAdd(&g_cursor[e], 1);
        g_perm_token[p] = i >> 1;
        g_inv[i] = p;
    } else if (i < T_TOK * 3) {
        int t = i - T_TOK * 2;
        g_perm_token[g_seg[NEXP] + t] = t;
    }
}

// ======================================================================
// fp16 mma.sync grouped GEMMs (256 threads, KC=64, ldmatrix.x4, 3-stage)
// gemm1 warp grid: 2(m) x 4(n), warp tile 64x32 -> min smem traffic for dual-B
// gemm2 warp grid: 4(m) x 2(n), warp tile 32x64
// ======================================================================

extern __shared__ __align__(16) __half smh[];

// stage 4: SwiGLU up-projection: ACT = silu(X W1) * (X W3), fp16 out
__global__ __launch_bounds__(256, 1) void gemm1_kernel(
    const __half* __restrict__ W1T, const __half* __restrict__ W3T,
    const __half* __restrict__ SW1T, const __half* __restrict__ SW3T) {
    int base = blockIdx.y * BM;
    if (base >= g_seg[NEXP + 1]) return;
    int e = 0;
    while (g_seg[e + 1] <= base) e++;
    const __half* W1e = (e < NEXP) ? W1T + (size_t)e * HID * DM : SW1T;
    const __half* W3e = (e < NEXP) ? W3T + (size_t)e * HID * DM : SW3T;
    int nb = blockIdx.x * BN;

    int tid = threadIdx.x, lane = tid & 31, warp = tid >> 5;
    int wm = warp >> 2, wn = warp & 3;     // 2x4 warps, warp tile 64(m)x32(n)

    uint32_t sbase = smem_u32(smh);

    // producer mapping: per tile 128 rows x 8 chunks(16B); 4 rows per thread
    int ch = tid & 7;
    int rows[4];
    const __half* asrc[4];
    uint32_t dstoff[4];
#pragma unroll
    for (int i = 0; i < 4; i++) {
        int r = (tid >> 3) + 32 * i;
        rows[i] = r;
        asrc[i] = g_xh + (size_t)g_perm_token[base + r] * DM + ch * 8;
        dstoff[i] = (uint32_t)(r * ROWB + ch * 16);
    }

    // A ldmatrix offsets: mt 0..3 covers rows wm*64 + mt*16
    uint32_t aoff[4];
#pragma unroll
    for (int mt = 0; mt < 4; mt++)
        aoff[mt] = (uint32_t)((wm * 64 + mt * 16 + (lane & 15)) * ROWB + (lane >> 4) * 16);
    // B ldmatrix.x4 offsets: p 0..1 covers n-rows [wn*32 + p*16, +16)
    uint32_t boff4[2];
#pragma unroll
    for (int p = 0; p < 2; p++)
        boff4[p] = (uint32_t)((wn * 32 + p * 16 + ((lane >> 4) & 1) * 8 + (lane & 7)) * ROWB
                              + ((lane >> 3) & 1) * 16);

    float acc1[4][4][4], acc3[4][4][4];
#pragma unroll
    for (int mt = 0; mt < 4; mt++)
#pragma unroll
        for (int nt = 0; nt < 4; nt++)
#pragma unroll
            for (int q = 0; q < 4; q++) { acc1[mt][nt][q] = 0.0f; acc3[mt][nt][q] = 0.0f; }

    const int nsl = DM / KC;   // 16

    auto issue = [&](int s) {
        uint32_t tb = sbase + (uint32_t)((s % STAGES) * 3 * SA * 2);
        int kb = s * KC;
#pragma unroll
        for (int i = 0; i < 4; i++) {
            cp16(tb + dstoff[i], asrc[i] + kb);
            cp16(tb + SA * 2 + dstoff[i], W1e + (size_t)(nb + rows[i]) * DM + kb + ch * 8);
            cp16(tb + 2 * SA * 2 + dstoff[i], W3e + (size_t)(nb + rows[i]) * DM + kb + ch * 8);
        }
        cp_commit();
    };

    issue(0);
    issue(1);

    for (int s = 0; s < nsl; s++) {
        if (s + 1 < nsl) cp_wait<1>(); else cp_wait<0>();
        __syncthreads();
        if (s + 2 < nsl) issue(s + 2);

        uint32_t tb = sbase + (uint32_t)((s % STAGES) * 3 * SA * 2);
        uint32_t aT = tb, b1T = tb + SA * 2, b3T = tb + 2 * SA * 2;
#pragma unroll
        for (int ks = 0; ks < 4; ks++) {
            uint32_t ko = ks * 32;   // 16 halves = 32 bytes
            unsigned b1[2][4], b3[2][4];
#pragma unroll
            for (int p = 0; p < 2; p++) {
                ldsm_x4(b1[p], b1T + boff4[p] + ko);
                ldsm_x4(b3[p], b3T + boff4[p] + ko);
            }
#pragma unroll
            for (int mt = 0; mt < 4; mt++) {
                unsigned a[4];
                ldsm_x4(a, aT + aoff[mt] + ko);
#pragma unroll
                for (int p = 0; p < 2; p++) {
                    mma_f16(acc1[mt][2 * p],     a, &b1[p][0]);
                    mma_f16(acc1[mt][2 * p + 1], a, &b1[p][2]);
                    mma_f16(acc3[mt][2 * p],     a, &b3[p][0]);
                    mma_f16(acc3[mt][2 * p + 1], a, &b3[p][2]);
                }
            }
        }
    }

    // epilogue: act = silu(h1) * h3, fp16
    int g = lane >> 2, tig = lane & 3;
#pragma unroll
    for (int mt = 0; mt < 4; mt++) {
#pragma unroll
        for (int nt = 0; nt < 4; nt++) {
            int r0 = base + wm * 64 + mt * 16 + g;
            int c  = nb + wn * 32 + nt * 8 + tig * 2;
            __half2 h0 = __floats2half2_rn(silu_f(acc1[mt][nt][0]) * acc3[mt][nt][0],
                                           silu_f(acc1[mt][nt][1]) * acc3[mt][nt][1]);
            __half2 h1 = __floats2half2_rn(silu_f(acc1[mt][nt][2]) * acc3[mt][nt][2],
                                           silu_f(acc1[mt][nt][3]) * acc3[mt][nt][3]);
            *reinterpret_cast<__half2*>(g_acth + (size_t)r0 * HID + c)       = h0;
            *reinterpret_cast<__half2*>(g_acth + (size_t)(r0 + 8) * HID + c) = h1;
        }
    }
}

// stage 5: down-projection: Y = ACT @ W2, fp32 out (4x2 warp grid, 32x64 tiles)
__global__ __launch_bounds__(256, 1) void gemm2_kernel(
    const __half* __restrict__ W2T, const __half* __restrict__ SW2T) {
    int base = blockIdx.y * BM;
    if (base >= g_seg[NEXP + 1]) return;
    int e = 0;
    while (g_seg[e + 1] <= base) e++;
    const __half* W2e = (e < NEXP) ? W2T + (size_t)e * DM * HID : SW2T;
    int nb = blockIdx.x * BN;

    int tid = threadIdx.x, lane = tid & 31, warp = tid >> 5;
    int wm = warp & 3, wn = warp >> 2;

    uint32_t sbase = smem_u32(smh);

    int ch = tid & 7;
    int rows[4];
    uint32_t dstoff[4];
#pragma unroll
    for (int i = 0; i < 4; i++) {
        int r = (tid >> 3) + 32 * i;
        rows[i] = r;
        dstoff[i] = (uint32_t)(r * ROWB + ch * 16);
    }

    uint32_t aoff[2];
#pragma unroll
    for (int mt = 0; mt < 2; mt++)
        aoff[mt] = (uint32_t)((wm * 32 + mt * 16 + (lane & 15)) * ROWB + (lane >> 4) * 16);
    uint32_t boff4[4];
#pragma unroll
    for (int p = 0; p < 4; p++)
        boff4[p] = (uint32_t)((wn * 64 + p * 16 + ((lane >> 4) & 1) * 8 + (lane & 7)) * ROWB
                              + ((lane >> 3) & 1) * 16);

    float acc[2][8][4];
#pragma unroll
    for (int mt = 0; mt < 2; mt++)
#pragma unroll
        for (int nt = 0; nt < 8; nt++)
#pragma unroll
            for (int q = 0; q < 4; q++) acc[mt][nt][q] = 0.0f;

    const int nsl = HID / KC;   // 32

    auto issue = [&](int s) {
        uint32_t tb = sbase + (uint32_t)((s % STAGES) * 2 * SA * 2);
        int kb = s * KC;
#pragma unroll
        for (int i = 0; i < 4; i++) {
            cp16(tb + dstoff[i], g_acth + (size_t)(base + rows[i]) * HID + kb + ch * 8);
            cp16(tb + SA * 2 + dstoff[i], W2e + (size_t)(nb + rows[i]) * HID + kb + ch * 8);
        }
        cp_commit();
    };

    issue(0);
    issue(1);

    for (int s = 0; s < nsl; s++) {
        if (s + 1 < nsl) cp_wait<1>(); else cp_wait<0>();
        __syncthreads();
        if (s + 2 < nsl) issue(s + 2);

        uint32_t tb = sbase + (uint32_t)((s % STAGES) * 2 * SA * 2);
        uint32_t aT = tb, bT = tb + SA * 2;
#pragma unroll
        for (int ks = 0; ks < 4; ks++) {
            uint32_t ko = ks * 32;
            unsigned a[2][4];
#pragma unroll
            for (int mt = 0; mt < 2; mt++) ldsm_x4(a[mt], aT + aoff[mt] + ko);
            unsigned b[4][4];
#pragma unroll
            for (int p = 0; p < 4; p++) ldsm_x4(b[p], bT + boff4[p] + ko);
#pragma unroll
            for (int mt = 0; mt < 2; mt++)
#pragma unroll
                for (int p = 0; p < 4; p++) {
                    mma_f16(acc[mt][2 * p],     a[mt], &b[p][0]);
                    mma_f16(acc[mt][2 * p + 1], a[mt], &b[p][2]);
                }
        }
    }

    int g = lane >> 2, tig = lane & 3;
#pragma unroll
    for (int mt = 0; mt < 2; mt++) {
#pragma unroll
        for (int nt = 0; nt < 8; nt++) {
            int r0 = base + wm * 32 + mt * 16 + g;
            int c  = nb + wn * 64 + nt * 8 + tig * 2;
            float2 o0, o1;
            o0.x = acc[mt][nt][0]; o0.y = acc[mt][nt][1];
            o1.x = acc[mt][nt][2]; o1.y = acc[mt][nt][3];
            *reinterpret_cast<float2*>(g_y + (size_t)r0 * DM + c)       = o0;
            *reinterpret_cast<float2*>(g_y + (size_t)(r0 + 8) * DM + c) = o1;
        }
    }
}

// ---------------- stage 6: combine shared + gated routed (float4) ----------------
__global__ void combine_kernel(float* __restrict__ OUT) {
    int i = blockIdx.x * blockDim.x + threadIdx.x;   // over float4s
    if (i >= T_TOK * DM / 4) return;
    int t  = i >> 8;            // DM/4 = 256 float4 per token
    int d4 = i & 255;
    int s8 = g_seg[NEXP];
    int p0 = g_inv[t * 2];
    int p1 = g_inv[t * 2 + 1];
    float g0 = g_topk_gate[t * 2];
    float g1 = g_topk_gate[t * 2 + 1];
    float4 vs = *reinterpret_cast<const float4*>(g_y + (size_t)(s8 + t) * DM + d4 * 4);
    float4 v0 = *reinterpret_cast<const float4*>(g_y + (size_t)p0 * DM + d4 * 4);
    float4 v1 = *reinterpret_cast<const float4*>(g_y + (size_t)p1 * DM + d4 * 4);
    float4 o;
    o.x = vs.x + g0 * v0.x + g1 * v1.x;
    o.y = vs.y + g0 * v0.y + g1 * v1.y;
    o.z = vs.z + g0 * v0.z + g1 * v1.z;
    o.w = vs.w + g0 * v0.w + g1 * v1.w;
    reinterpret_cast<float4*>(OUT)[i] = o;
}

// ---------------- launch ----------------
#define G1_SMEM (STAGES * 3 * SA * 2)   // 165888 bytes
#define G2_SMEM (STAGES * 2 * SA * 2)   // 110592 bytes

extern "C" void kernel_launch(void* const* d_in, const int* in_sizes, int n_in,
                              void* d_out, int out_size) {
    (void)in_sizes; (void)n_in; (void)out_size;
    const float* x   = (const float*)d_in[0];
    const float* wr  = (const float*)d_in[1];
    const float* w1  = (const float*)d_in[2];
    const float* w3  = (const float*)d_in[3];
    const float* w2  = (const float*)d_in[4];
    const float* sw1 = (const float*)d_in[5];
    const float* sw3 = (const float*)d_in[6];
    const float* sw2 = (const float*)d_in[7];
    float* out = (float*)d_out;

    __half *w1t, *w3t, *w2t, *sw1t, *sw3t, *sw2t;
    cudaGetSymbolAddress((void**)&w1t,  g_w1t);
    cudaGetSymbolAddress((void**)&w3t,  g_w3t);
    cudaGetSymbolAddress((void**)&w2t,  g_w2t);
    cudaGetSymbolAddress((void**)&sw1t, g_sw1t);
    cudaGetSymbolAddress((void**)&sw3t, g_sw3t);
    cudaGetSymbolAddress((void**)&sw2t, g_sw2t);

    cudaFuncSetAttribute(gemm1_kernel, cudaFuncAttributeMaxDynamicSharedMemorySize, G1_SMEM);
    cudaFuncSetAttribute(gemm2_kernel, cudaFuncAttributeMaxDynamicSharedMemorySize, G2_SMEM);

    reset_kernel<<<52, 256>>>();
    router_kernel<<<512, 256>>>(x, wr);
    scan_kernel<<<1, 32>>>();
    fill_kernel<<<48, 256>>>();

    cvt_x_kernel<<<(T_TOK * DM / 4) / 256, 256>>>(x);
    transpose_up_kernel<<<dim3(HID / 64, DM / 64, 18), 256>>>(w1, w3, sw1, sw3);
    transpose_down_kernel<<<dim3(DM / 64, HID / 64, 9), 256>>>(w2, sw2);

    gemm1_kernel<<<dim3(HID / BN, MAXROWS / BM), 256, G1_SMEM>>>(w1t, w3t, sw1t, sw3t);
    gemm2_kernel<<<dim3(DM / BN, MAXROWS / BM), 256, G2_SMEM>>>(w2t, sw2t);

    combine_kernel<<<(T_TOK * DM / 4 + 255) / 256, 256>>>(out);
}

// round 14
// speedup vs baseline: 1.0435x; 1.0191x over previous
#include <cuda_runtime.h>
#include <cuda_fp16.h>
#include <cstdint>

// Problem constants
#define T_TOK   4096
#define DM      1024
#define HID     2048
#define NEXP    8
#define PADMAX  9216
#define MAXROWS (PADMAX + T_TOK)     // 13312

// GEMM tiling (half-precision element counts)
#define BM 128
#define BN 128
#define KC 64               // halves per k-slice
#define ASTR 72             // row stride in halves (64 + 8 pad; 144B rows, conflict-free)
#define ROWB (ASTR * 2)     // 144 bytes
#define STAGES 3
#define SA (BM * ASTR)      // halves per tile (9216)

// ---------------- scratch (device globals: allocation-free) ----------------
__device__ int    g_counts[NEXP];
__device__ int    g_seg[NEXP + 2];
__device__ int    g_cursor[NEXP];
__device__ int    g_topk_idx[T_TOK * 2];
__device__ float  g_topk_gate[T_TOK * 2];
__device__ int    g_perm_token[MAXROWS];
__device__ int    g_inv[T_TOK * 2];
__device__ __half g_xh[(size_t)T_TOK * DM];           // fp16 X
__device__ __half g_w1t[(size_t)NEXP * HID * DM];     // [e][h][d]
__device__ __half g_w3t[(size_t)NEXP * HID * DM];
__device__ __half g_w2t[(size_t)NEXP * DM * HID];     // [e][d][h]
__device__ __half g_sw1t[(size_t)HID * DM];
__device__ __half g_sw3t[(size_t)HID * DM];
__device__ __half g_sw2t[(size_t)DM * HID];
__device__ __half g_acth[(size_t)MAXROWS * HID];      // fp16 SwiGLU activations
__device__ float  g_y[(size_t)MAXROWS * DM];          // fp32 expert outputs

// ---------------- helpers ----------------
__device__ __forceinline__ uint32_t smem_u32(const void* p) {
    return (uint32_t)__cvta_generic_to_shared(p);
}
__device__ __forceinline__ void mma_f16(float* d, const unsigned* a, const unsigned* b) {
    asm volatile(
        "mma.sync.aligned.m16n8k16.row.col.f32.f16.f16.f32 "
        "{%0,%1,%2,%3}, {%4,%5,%6,%7}, {%8,%9}, {%0,%1,%2,%3};\n"
        : "+f"(d[0]), "+f"(d[1]), "+f"(d[2]), "+f"(d[3])
        : "r"(a[0]), "r"(a[1]), "r"(a[2]), "r"(a[3]), "r"(b[0]), "r"(b[1]));
}
__device__ __forceinline__ void ldsm_x4(unsigned* r, uint32_t addr) {
    asm volatile("ldmatrix.sync.aligned.m8n8.x4.shared.b16 {%0,%1,%2,%3}, [%4];"
                 : "=r"(r[0]), "=r"(r[1]), "=r"(r[2]), "=r"(r[3]) : "r"(addr));
}
__device__ __forceinline__ void cp16(uint32_t dst, const __half* src) {
    asm volatile("cp.async.cg.shared.global [%0], [%1], 16;\n" :: "r"(dst), "l"(src));
}
__device__ __forceinline__ void cp_commit() { asm volatile("cp.async.commit_group;\n"); }
template <int N> __device__ __forceinline__ void cp_wait() {
    asm volatile("cp.async.wait_group %0;\n" :: "n"(N));
}
__device__ __forceinline__ float silu_f(float h) {
    return __fdividef(h, 1.0f + __expf(-h));
}

// ---------------- stage 0: reset ----------------
__global__ void reset_kernel() {
    int i = blockIdx.x * blockDim.x + threadIdx.x;
    if (i < NEXP) g_counts[i] = 0;
    for (int p = i; p < MAXROWS; p += gridDim.x * blockDim.x) g_perm_token[p] = 0;
}

// ---------------- convert X -> fp16 ----------------
__global__ void cvt_x_kernel(const float* __restrict__ X) {
    int i = blockIdx.x * blockDim.x + threadIdx.x;
    float4 v = reinterpret_cast<const float4*>(X)[i];
    __half2* dst = reinterpret_cast<__half2*>(g_xh);
    dst[2 * i]     = __floats2half2_rn(v.x, v.y);
    dst[2 * i + 1] = __floats2half2_rn(v.z, v.w);
}

// ---------------- convert + transpose: in[R][C] fp32 -> out[C][R] fp16 ----------------
__device__ __forceinline__ void transpose_cvt_body(
    const float* __restrict__ in, __half* __restrict__ out, int R, int C) {
    __shared__ __half tile[64][66];
    int c0 = blockIdx.x * 64, r0 = blockIdx.y * 64;

    int fc = threadIdx.x & 15, row4 = threadIdx.x >> 4;
#pragma unroll
    for (int p = 0; p < 4; p++) {
        int r = row4 + p * 16;
        float4 v = *reinterpret_cast<const float4*>(in + (size_t)(r0 + r) * C + c0 + fc * 4);
        tile[fc * 4 + 0][r] = __float2half_rn(v.x);
        tile[fc * 4 + 1][r] = __float2half_rn(v.y);
        tile[fc * 4 + 2][r] = __float2half_rn(v.z);
        tile[fc * 4 + 3][r] = __float2half_rn(v.w);
    }
    __syncthreads();

    int oc = threadIdx.x >> 2, seg = threadIdx.x & 3;
    unsigned u[8];
#pragma unroll
    for (int j = 0; j < 8; j++) {
        __half2 hh = __halves2half2(tile[oc][seg * 16 + 2 * j], tile[oc][seg * 16 + 2 * j + 1]);
        u[j] = *reinterpret_cast<unsigned*>(&hh);
    }
    uint4* dst = reinterpret_cast<uint4*>(out + (size_t)(c0 + oc) * R + r0 + seg * 16);
    dst[0] = make_uint4(u[0], u[1], u[2], u[3]);
    dst[1] = make_uint4(u[4], u[5], u[6], u[7]);
}

// merged: all up-projection weights (w1 x8, w3 x8, sw1, sw3); R=DM, C=HID
__global__ __launch_bounds__(256) void transpose_up_kernel(
    const float* __restrict__ w1, const float* __restrict__ w3,
    const float* __restrict__ sw1, const float* __restrict__ sw3) {
    int z = blockIdx.z;
    const float* in;
    __half* out;
    if (z < 8)       { in = w1 + (size_t)z * DM * HID;        out = g_w1t + (size_t)z * HID * DM; }
    else if (z < 16) { in = w3 + (size_t)(z - 8) * DM * HID;  out = g_w3t + (size_t)(z - 8) * HID * DM; }
    else if (z == 16){ in = sw1;                              out = g_sw1t; }
    else             { in = sw3;                              out = g_sw3t; }
    transpose_cvt_body(in, out, DM, HID);
}

// merged: all down-projection weights (w2 x8, sw2); R=HID, C=DM
__global__ __launch_bounds__(256) void transpose_down_kernel(
    const float* __restrict__ w2, const float* __restrict__ sw2) {
    int z = blockIdx.z;
    const float* in;
    __half* out;
    if (z < 8) { in = w2 + (size_t)z * HID * DM; out = g_w2t + (size_t)z * DM * HID; }
    else       { in = sw2;                       out = g_sw2t; }
    transpose_cvt_body(in, out, HID, DM);
}

// ---------------- stage 1: router ----------------
__global__ __launch_bounds__(256) void router_kernel(const float* __restrict__ X,
                                                     const float* __restrict__ WR) {
    int warp = threadIdx.x >> 5, lane = threadIdx.x & 31;
    int t = blockIdx.x * 8 + warp;
    if (t >= T_TOK) return;

    float acc[8];
#pragma unroll
    for (int e = 0; e < 8; e++) acc[e] = 0.0f;

    const float* xr = X + (size_t)t * DM;
    for (int i = lane; i < DM; i += 32) {
        float xv = xr[i];
        const float4* w = reinterpret_cast<const float4*>(WR + (size_t)i * NEXP);
        float4 w0 = w[0], w1 = w[1];
        acc[0] += xv * w0.x; acc[1] += xv * w0.y; acc[2] += xv * w0.z; acc[3] += xv * w0.w;
        acc[4] += xv * w1.x; acc[5] += xv * w1.y; acc[6] += xv * w1.z; acc[7] += xv * w1.w;
    }
#pragma unroll
    for (int e = 0; e < 8; e++)
#pragma unroll
        for (int off = 16; off > 0; off >>= 1)
            acc[e] += __shfl_xor_sync(0xffffffffu, acc[e], off);

    if (lane == 0) {
        int i0 = 0; float v0 = acc[0];
#pragma unroll
        for (int e = 1; e < 8; e++) if (acc[e] > v0) { v0 = acc[e]; i0 = e; }
        int i1 = -1; float v1 = -3.4e38f;
#pragma unroll
        for (int e = 0; e < 8; e++) if (e != i0 && acc[e] > v1) { v1 = acc[e]; i1 = e; }
        float r  = expf(v1 - v0);
        float g0 = 1.0f / (1.0f + r);
        float g1 = r / (1.0f + r);
        g_topk_idx[t * 2]      = i0;
        g_topk_idx[t * 2 + 1]  = i1;
        g_topk_gate[t * 2]     = g0;
        g_topk_gate[t * 2 + 1] = g1;
        atomicAdd(&g_counts[i0], 1);
        atomicAdd(&g_counts[i1], 1);
    }
}

// ---------------- stage 2: segment scan ----------------
__global__ void scan_kernel() {
    if (threadIdx.x == 0 && blockIdx.x == 0) {
        int s = 0;
        for (int e = 0; e < NEXP; e++) {
            g_seg[e] = s;
            g_cursor[e] = s;
            s += (g_counts[e] + BM - 1) & ~(BM - 1);
        }
        g_seg[NEXP] = s;
        g_seg[NEXP + 1] = s + T_TOK;
    }
}

// ---------------- stage 3: build permutation ----------------
__global__ void fill_kernel() {
    int i = blockIdx.x * blockDim.x + threadIdx.x;
    if (i < T_TOK * 2) {
        int e = g_topk_idx[i];
        int p = atomicAdd(&g_cursor[e], 1);
        g_perm_token[p] = i >> 1;
        g_inv[i] = p;
    } else if (i < T_TOK * 3) {
        int t = i - T_TOK * 2;
        g_perm_token[g_seg[NEXP] + t] = t;
    }
}

// ======================================================================
// fp16 mma.sync grouped GEMMs (256 threads, KC=64, ldmatrix.x4, 3-stage)
// gemm1 warp grid: 2(m) x 4(n), warp tile 64x32
// gemm2 warp grid: 4(m) x 2(n), warp tile 32x64
// ======================================================================

extern __shared__ __align__(16) __half smh[];

// stage 4: SwiGLU up-projection: ACT = silu(X W1) * (X W3), fp16 out
__global__ __launch_bounds__(256, 1) void gemm1_kernel(
    const __half* __restrict__ W1T, const __half* __restrict__ W3T,
    const __half* __restrict__ SW1T, const __half* __restrict__ SW3T) {
    int base = blockIdx.y * BM;
    if (base >= g_seg[NEXP + 1]) return;
    int e = 0;
    while (g_seg[e + 1] <= base) e++;
    const __half* W1e = (e < NEXP) ? W1T + (size_t)e * HID * DM : SW1T;
    const __half* W3e = (e < NEXP) ? W3T + (size_t)e * HID * DM : SW3T;
    int nb = blockIdx.x * BN;

    int tid = threadIdx.x, lane = tid & 31, warp = tid >> 5;
    int wm = warp >> 2, wn = warp & 3;     // 2x4 warps, warp tile 64(m)x32(n)

    uint32_t sbase = smem_u32(smh);

    // producer mapping: per tile 128 rows x 8 chunks(16B); 4 rows per thread
    int ch = tid & 7;
    int rows[4];
    const __half* asrc[4];
    uint32_t dstoff[4];
#pragma unroll
    for (int i = 0; i < 4; i++) {
        int r = (tid >> 3) + 32 * i;
        rows[i] = r;
        asrc[i] = g_xh + (size_t)g_perm_token[base + r] * DM + ch * 8;
        dstoff[i] = (uint32_t)(r * ROWB + ch * 16);
    }

    // A ldmatrix offsets: mt 0..3 covers rows wm*64 + mt*16
    uint32_t aoff[4];
#pragma unroll
    for (int mt = 0; mt < 4; mt++)
        aoff[mt] = (uint32_t)((wm * 64 + mt * 16 + (lane & 15)) * ROWB + (lane >> 4) * 16);
    // B ldmatrix.x4 offsets: p 0..1 covers n-rows [wn*32 + p*16, +16)
    uint32_t boff4[2];
#pragma unroll
    for (int p = 0; p < 2; p++)
        boff4[p] = (uint32_t)((wn * 32 + p * 16 + ((lane >> 4) & 1) * 8 + (lane & 7)) * ROWB
                              + ((lane >> 3) & 1) * 16);

    float acc1[4][4][4], acc3[4][4][4];
#pragma unroll
    for (int mt = 0; mt < 4; mt++)
#pragma unroll
        for (int nt = 0; nt < 4; nt++)
#pragma unroll
            for (int q = 0; q < 4; q++) { acc1[mt][nt][q] = 0.0f; acc3[mt][nt][q] = 0.0f; }

    const int nsl = DM / KC;   // 16

    auto issue = [&](int s) {
        uint32_t tb = sbase + (uint32_t)((s % STAGES) * 3 * SA * 2);
        int kb = s * KC;
#pragma unroll
        for (int i = 0; i < 4; i++) {
            cp16(tb + dstoff[i], asrc[i] + kb);
            cp16(tb + SA * 2 + dstoff[i], W1e + (size_t)(nb + rows[i]) * DM + kb + ch * 8);
            cp16(tb + 2 * SA * 2 + dstoff[i], W3e + (size_t)(nb + rows[i]) * DM + kb + ch * 8);
        }
        cp_commit();
    };

    issue(0);
    issue(1);

    for (int s = 0; s < nsl; s++) {
        if (s + 1 < nsl) cp_wait<1>(); else cp_wait<0>();
        __syncthreads();
        if (s + 2 < nsl) issue(s + 2);

        uint32_t tb = sbase + (uint32_t)((s % STAGES) * 3 * SA * 2);
        uint32_t aT = tb, b1T = tb + SA * 2, b3T = tb + 2 * SA * 2;
#pragma unroll
        for (int ks = 0; ks < 4; ks++) {
            uint32_t ko = ks * 32;   // 16 halves = 32 bytes
            unsigned b1[2][4], b3[2][4];
#pragma unroll
            for (int p = 0; p < 2; p++) {
                ldsm_x4(b1[p], b1T + boff4[p] + ko);
                ldsm_x4(b3[p], b3T + boff4[p] + ko);
            }
#pragma unroll
            for (int mt = 0; mt < 4; mt++) {
                unsigned a[4];
                ldsm_x4(a, aT + aoff[mt] + ko);
#pragma unroll
                for (int p = 0; p < 2; p++) {
                    mma_f16(acc1[mt][2 * p],     a, &b1[p][0]);
                    mma_f16(acc1[mt][2 * p + 1], a, &b1[p][2]);
                    mma_f16(acc3[mt][2 * p],     a, &b3[p][0]);
                    mma_f16(acc3[mt][2 * p + 1], a, &b3[p][2]);
                }
            }
        }
    }

    // epilogue: act = silu(h1) * h3, fp16
    int g = lane >> 2, tig = lane & 3;
#pragma unroll
    for (int mt = 0; mt < 4; mt++) {
#pragma unroll
        for (int nt = 0; nt < 4; nt++) {
            int r0 = base + wm * 64 + mt * 16 + g;
            int c  = nb + wn * 32 + nt * 8 + tig * 2;
            __half2 h0 = __floats2half2_rn(silu_f(acc1[mt][nt][0]) * acc3[mt][nt][0],
                                           silu_f(acc1[mt][nt][1]) * acc3[mt][nt][1]);
            __half2 h1 = __floats2half2_rn(silu_f(acc1[mt][nt][2]) * acc3[mt][nt][2],
                                           silu_f(acc1[mt][nt][3]) * acc3[mt][nt][3]);
            *reinterpret_cast<__half2*>(g_acth + (size_t)r0 * HID + c)       = h0;
            *reinterpret_cast<__half2*>(g_acth + (size_t)(r0 + 8) * HID + c) = h1;
        }
    }
}

// stage 5: down-projection: Y = ACT @ W2, fp32 out (4x2 warp grid, 32x64 tiles)
__global__ __launch_bounds__(256, 1) void gemm2_kernel(
    const __half* __restrict__ W2T, const __half* __restrict__ SW2T) {
    int base = blockIdx.y * BM;
    if (base >= g_seg[NEXP + 1]) return;
    int e = 0;
    while (g_seg[e + 1] <= base) e++;
    const __half* W2e = (e < NEXP) ? W2T + (size_t)e * DM * HID : SW2T;
    int nb = blockIdx.x * BN;

    int tid = threadIdx.x, lane = tid & 31, warp = tid >> 5;
    int wm = warp & 3, wn = warp >> 2;

    uint32_t sbase = smem_u32(smh);

    int ch = tid & 7;
    int rows[4];
    uint32_t dstoff[4];
#pragma unroll
    for (int i = 0; i < 4; i++) {
        int r = (tid >> 3) + 32 * i;
        rows[i] = r;
        dstoff[i] = (uint32_t)(r * ROWB + ch * 16);
    }

    uint32_t aoff[2];
#pragma unroll
    for (int mt = 0; mt < 2; mt++)
        aoff[mt] = (uint32_t)((wm * 32 + mt * 16 + (lane & 15)) * ROWB + (lane >> 4) * 16);
    uint32_t boff4[4];
#pragma unroll
    for (int p = 0; p < 4; p++)
        boff4[p] = (uint32_t)((wn * 64 + p * 16 + ((lane >> 4) & 1) * 8 + (lane & 7)) * ROWB
                              + ((lane >> 3) & 1) * 16);

    float acc[2][8][4];
#pragma unroll
    for (int mt = 0; mt < 2; mt++)
#pragma unroll
        for (int nt = 0; nt < 8; nt++)
#pragma unroll
            for (int q = 0; q < 4; q++) acc[mt][nt][q] = 0.0f;

    const int nsl = HID / KC;   // 32

    auto issue = [&](int s) {
        uint32_t tb = sbase + (uint32_t)((s % STAGES) * 2 * SA * 2);
        int kb = s * KC;
#pragma unroll
        for (int i = 0; i < 4; i++) {
            cp16(tb + dstoff[i], g_acth + (size_t)(base + rows[i]) * HID + kb + ch * 8);
            cp16(tb + SA * 2 + dstoff[i], W2e + (size_t)(nb + rows[i]) * HID + kb + ch * 8);
        }
        cp_commit();
    };

    issue(0);
    issue(1);

    for (int s = 0; s < nsl; s++) {
        if (s + 1 < nsl) cp_wait<1>(); else cp_wait<0>();
        __syncthreads();
        if (s + 2 < nsl) issue(s + 2);

        uint32_t tb = sbase + (uint32_t)((s % STAGES) * 2 * SA * 2);
        uint32_t aT = tb, bT = tb + SA * 2;
#pragma unroll
        for (int ks = 0; ks < 4; ks++) {
            uint32_t ko = ks * 32;
            unsigned a[2][4];
#pragma unroll
            for (int mt = 0; mt < 2; mt++) ldsm_x4(a[mt], aT + aoff[mt] + ko);
            unsigned b[4][4];
#pragma unroll
            for (int p = 0; p < 4; p++) ldsm_x4(b[p], bT + boff4[p] + ko);
#pragma unroll
            for (int mt = 0; mt < 2; mt++)
#pragma unroll
                for (int p = 0; p < 4; p++) {
                    mma_f16(acc[mt][2 * p],     a[mt], &b[p][0]);
                    mma_f16(acc[mt][2 * p + 1], a[mt], &b[p][2]);
                }
        }
    }

    int g = lane >> 2, tig = lane & 3;
#pragma unroll
    for (int mt = 0; mt < 2; mt++) {
#pragma unroll
        for (int nt = 0; nt < 8; nt++) {
            int r0 = base + wm * 32 + mt * 16 + g;
            int c  = nb + wn * 64 + nt * 8 + tig * 2;
            float2 o0, o1;
            o0.x = acc[mt][nt][0]; o0.y = acc[mt][nt][1];
            o1.x = acc[mt][nt][2]; o1.y = acc[mt][nt][3];
            *reinterpret_cast<float2*>(g_y + (size_t)r0 * DM + c)       = o0;
            *reinterpret_cast<float2*>(g_y + (size_t)(r0 + 8) * DM + c) = o1;
        }
    }
}

// ---------------- stage 6: combine shared + gated routed (float4) ----------------
__global__ void combine_kernel(float* __restrict__ OUT) {
    int i = blockIdx.x * blockDim.x + threadIdx.x;   // over float4s
    if (i >= T_TOK * DM / 4) return;
    int t  = i >> 8;            // DM/4 = 256 float4 per token
    int d4 = i & 255;
    int s8 = g_seg[NEXP];
    int p0 = g_inv[t * 2];
    int p1 = g_inv[t * 2 + 1];
    float g0 = g_topk_gate[t * 2];
    float g1 = g_topk_gate[t * 2 + 1];
    float4 vs = *reinterpret_cast<const float4*>(g_y + (size_t)(s8 + t) * DM + d4 * 4);
    float4 v0 = *reinterpret_cast<const float4*>(g_y + (size_t)p0 * DM + d4 * 4);
    float4 v1 = *reinterpret_cast<const float4*>(g_y + (size_t)p1 * DM + d4 * 4);
    float4 o;
    o.x = vs.x + g0 * v0.x + g1 * v1.x;
    o.y = vs.y + g0 * v0.y + g1 * v1.y;
    o.z = vs.z + g0 * v0.z + g1 * v1.z;
    o.w = vs.w + g0 * v0.w + g1 * v1.w;
    reinterpret_cast<float4*>(OUT)[i] = o;
}

// ---------------- launch ----------------
#define G1_SMEM (STAGES * 3 * SA * 2)   // 165888 bytes
#define G2_SMEM (STAGES * 2 * SA * 2)   // 110592 bytes

extern "C" void kernel_launch(void* const* d_in, const int* in_sizes, int n_in,
                              void* d_out, int out_size) {
    (void)in_sizes; (void)n_in; (void)out_size;
    const float* x   = (const float*)d_in[0];
    const float* wr  = (const float*)d_in[1];
    const float* w1  = (const float*)d_in[2];
    const float* w3  = (const float*)d_in[3];
    const float* w2  = (const float*)d_in[4];
    const float* sw1 = (const float*)d_in[5];
    const float* sw3 = (const float*)d_in[6];
    const float* sw2 = (const float*)d_in[7];
    float* out = (float*)d_out;

    __half *w1t, *w3t, *w2t, *sw1t, *sw3t, *sw2t;
    cudaGetSymbolAddress((void**)&w1t,  g_w1t);
    cudaGetSymbolAddress((void**)&w3t,  g_w3t);
    cudaGetSymbolAddress((void**)&w2t,  g_w2t);
    cudaGetSymbolAddress((void**)&sw1t, g_sw1t);
    cudaGetSymbolAddress((void**)&sw3t, g_sw3t);
    cudaGetSymbolAddress((void**)&sw2t, g_sw2t);

    cudaFuncSetAttribute(gemm1_kernel, cudaFuncAttributeMaxDynamicSharedMemorySize, G1_SMEM);
    cudaFuncSetAttribute(gemm2_kernel, cudaFuncAttributeMaxDynamicSharedMemorySize, G2_SMEM);

    // fork-join: branch A (routing chain) on base stream, branch B (conversion)
    // on a side stream. Events become graph dependencies under capture.
    // Host-side objects only; created per call (deterministic), not destroyed
    // mid-capture.
    cudaStream_t s2;
    cudaStreamCreateWithFlags(&s2, cudaStreamNonBlocking);
    cudaEvent_t evFork, evUp, evDown;
    cudaEventCreateWithFlags(&evFork, cudaEventDisableTiming);
    cudaEventCreateWithFlags(&evUp,   cudaEventDisableTiming);
    cudaEventCreateWithFlags(&evDown, cudaEventDisableTiming);

    cudaEventRecord(evFork, 0);
    cudaStreamWaitEvent(s2, evFork, 0);

    // branch B (side stream): conversions
    cvt_x_kernel<<<(T_TOK * DM / 4) / 256, 256, 0, s2>>>(x);
    transpose_up_kernel<<<dim3(HID / 64, DM / 64, 18), 256, 0, s2>>>(w1, w3, sw1, sw3);
    cudaEventRecord(evUp, s2);
    transpose_down_kernel<<<dim3(DM / 64, HID / 64, 9), 256, 0, s2>>>(w2, sw2);
    cudaEventRecord(evDown, s2);

    // branch A (base stream): routing
    reset_kernel<<<52, 256>>>();
    router_kernel<<<512, 256>>>(x, wr);
    scan_kernel<<<1, 32>>>();
    fill_kernel<<<48, 256>>>();

    // gemm1 needs routing + X/up-weights; transpose_down overlaps gemm1
    cudaStreamWaitEvent(0, evUp, 0);
    gemm1_kernel<<<dim3(HID / BN, MAXROWS / BM), 256, G1_SMEM>>>(w1t, w3t, sw1t, sw3t);
    cudaStreamWaitEvent(0, evDown, 0);
    gemm2_kernel<<<dim3(DM / BN, MAXROWS / BM), 256, G2_SMEM>>>(w2t, sw2t);

    combine_kernel<<<(T_TOK * DM / 4 + 255) / 256, 256>>>(out);
}